// round 10
// baseline (speedup 1.0000x reference)
#include <cuda_runtime.h>
#include <cuda_bf16.h>
#include <math.h>
#include <stdint.h>

// Problem constants
#define BB 16
#define CC 512
#define CB 64
#define NN 4096
#define NT 32    // n-tiles of 128 per batch

// ---------------------------------------------------------------------------
// Scratch (static __device__ arrays — no runtime allocation)
// ---------------------------------------------------------------------------
__device__ __align__(16) __nv_bfloat16 g_v_hi[BB * CB * NN];   // 8 MB
__device__ __align__(16) __nv_bfloat16 g_v_lo[BB * CB * NN];   // 8 MB
__device__ float g_lp[BB * NT * CB * CB];                      // 8 MB
__device__ float g_logits[BB * CB * CB];                       // 256 KB
__device__ __align__(16) __nv_bfloat16 g_M_hi[BB * CC * CB];   // 1 MB
__device__ __align__(16) __nv_bfloat16 g_M_lo[BB * CC * CB];   // 1 MB

// ---------------------------------------------------------------------------
// MMA helpers (warp mma, bf16 in / fp32 accum)
// ---------------------------------------------------------------------------
__device__ __forceinline__ uint32_t sptr(const void* p) {
    return (uint32_t)__cvta_generic_to_shared(p);
}
__device__ __forceinline__ void ldm4(uint32_t* r, uint32_t a) {
    asm volatile("ldmatrix.sync.aligned.m8n8.x4.shared.b16 {%0,%1,%2,%3}, [%4];"
        : "=r"(r[0]), "=r"(r[1]), "=r"(r[2]), "=r"(r[3]) : "r"(a));
}
__device__ __forceinline__ void ldm4t(uint32_t* r, uint32_t a) {
    asm volatile("ldmatrix.sync.aligned.m8n8.x4.trans.shared.b16 {%0,%1,%2,%3}, [%4];"
        : "=r"(r[0]), "=r"(r[1]), "=r"(r[2]), "=r"(r[3]) : "r"(a));
}
__device__ __forceinline__ void mma16816(float* c, const uint32_t* a, const uint32_t* b) {
    asm volatile("mma.sync.aligned.m16n8k16.row.col.f32.bf16.bf16.f32 "
        "{%0,%1,%2,%3}, {%4,%5,%6,%7}, {%8,%9}, {%0,%1,%2,%3};"
        : "+f"(c[0]), "+f"(c[1]), "+f"(c[2]), "+f"(c[3])
        : "r"(a[0]), "r"(a[1]), "r"(a[2]), "r"(a[3]), "r"(b[0]), "r"(b[1]));
}
__device__ __forceinline__ void split2(float v, __nv_bfloat16& h, __nv_bfloat16& l) {
    h = __float2bfloat16_rn(v);
    l = __float2bfloat16_rn(v - __bfloat162float(h));
}

#define WS 40     // W smem row stride (bf16)
#define XS 136    // X/V smem row stride (bf16)
#define QS 72     // Q/K smem row stride (bf16)
#define MS 40     // M smem row stride (bf16)

// ---------------------------------------------------------------------------
// Kernel 1: fused QKV projection (bf16x3 mma) + logits partial (bf16x3 mma).
// EXACT R3 configuration (measured 175.6us).
// grid (32, 16), block 256 (8 warps).  Warp grid 2m x 4n, warp tile 96x32.
// ---------------------------------------------------------------------------
__global__ __launch_bounds__(256, 1) void qkv_logits_kernel(
    const float* __restrict__ x,
    const float* __restrict__ wq, const float* __restrict__ bq,
    const float* __restrict__ wk, const float* __restrict__ bk,
    const float* __restrict__ wv, const float* __restrict__ bv)
{
    __shared__ __align__(16) __nv_bfloat16 smem[24064];  // 48128 B
    // phase 1 layout
    __nv_bfloat16* Whi = smem;            // [192][40]
    __nv_bfloat16* Wlo = smem + 7680;
    __nv_bfloat16* Xhi = smem + 15360;    // [32][136]
    __nv_bfloat16* Xlo = smem + 19712;
    // phase 2 layout (union; phase 1 data dead by then)
    __nv_bfloat16* Qhi = smem;            // [64][72] x4
    __nv_bfloat16* Qlo = smem + 4608;
    __nv_bfloat16* Khi = smem + 9216;
    __nv_bfloat16* Klo = smem + 13824;

    const int b = blockIdx.y, ntile = blockIdx.x;
    const int n_base = ntile * 128;
    const int tid = threadIdx.x, lane = tid & 31, wid = tid >> 5;
    const int wm = wid >> 2, wn = wid & 3;     // warp grid 2m x 4n
    const int g = lane >> 3, r = lane & 7;     // ldmatrix addressing
    const int q_r = lane >> 2, q_c = (lane & 3) * 2;  // C-fragment coords

    const float* xb = x + (size_t)b * CC * NN;

    float acc[6][4][4];
    #pragma unroll
    for (int i = 0; i < 6; i++)
        #pragma unroll
        for (int j = 0; j < 4; j++)
            #pragma unroll
            for (int e = 0; e < 4; e++) acc[i][j][e] = 0.f;

    for (int kc = 0; kc < 16; kc++) {
        const int k0 = kc * 32;
        // ---- load & split W chunk [192 m][32 k] ----
        #pragma unroll
        for (int i = 0; i < 6; i++) {
            int idx4 = i * 256 + tid;            // 0..1535
            int m = idx4 >> 3, kq = (idx4 & 7) * 4;
            const float* src;
            if (m < 64)       src = wq + m * CC;
            else if (m < 128) src = wk + (m - 64) * CC;
            else              src = wv + (m - 128) * CC;
            float4 v = *reinterpret_cast<const float4*>(src + k0 + kq);
            __nv_bfloat16 h0, l0, h1, l1, h2, l2, h3, l3;
            split2(v.x, h0, l0); split2(v.y, h1, l1);
            split2(v.z, h2, l2); split2(v.w, h3, l3);
            __nv_bfloat16* dh = Whi + m * WS + kq;
            __nv_bfloat16* dl = Wlo + m * WS + kq;
            *reinterpret_cast<__nv_bfloat162*>(dh)     = __nv_bfloat162(h0, h1);
            *reinterpret_cast<__nv_bfloat162*>(dh + 2) = __nv_bfloat162(h2, h3);
            *reinterpret_cast<__nv_bfloat162*>(dl)     = __nv_bfloat162(l0, l1);
            *reinterpret_cast<__nv_bfloat162*>(dl + 2) = __nv_bfloat162(l2, l3);
        }
        // ---- load & split X chunk [32 k][128 n] ----
        #pragma unroll
        for (int i = 0; i < 4; i++) {
            int idx4 = i * 256 + tid;            // 0..1023
            int k = idx4 >> 5, n4 = (idx4 & 31) * 4;
            float4 v = *reinterpret_cast<const float4*>(
                xb + (size_t)(k0 + k) * NN + n_base + n4);
            __nv_bfloat16 h0, l0, h1, l1, h2, l2, h3, l3;
            split2(v.x, h0, l0); split2(v.y, h1, l1);
            split2(v.z, h2, l2); split2(v.w, h3, l3);
            __nv_bfloat16* dh = Xhi + k * XS + n4;
            __nv_bfloat16* dl = Xlo + k * XS + n4;
            *reinterpret_cast<__nv_bfloat162*>(dh)     = __nv_bfloat162(h0, h1);
            *reinterpret_cast<__nv_bfloat162*>(dh + 2) = __nv_bfloat162(h2, h3);
            *reinterpret_cast<__nv_bfloat162*>(dl)     = __nv_bfloat162(l0, l1);
            *reinterpret_cast<__nv_bfloat162*>(dl + 2) = __nv_bfloat162(l2, l3);
        }
        __syncthreads();

        #pragma unroll
        for (int ks = 0; ks < 2; ks++) {
            const int kk = ks * 16;
            uint32_t Bh[4][2], Bl[4][2];
            #pragma unroll
            for (int nt2 = 0; nt2 < 2; nt2++) {
                int row = kk + (g & 1) * 8 + r;
                int col = wn * 32 + nt2 * 16 + (g >> 1) * 8;
                uint32_t t[4];
                ldm4t(t, sptr(Xhi + row * XS + col));
                Bh[nt2*2][0]=t[0]; Bh[nt2*2][1]=t[1]; Bh[nt2*2+1][0]=t[2]; Bh[nt2*2+1][1]=t[3];
                ldm4t(t, sptr(Xlo + row * XS + col));
                Bl[nt2*2][0]=t[0]; Bl[nt2*2][1]=t[1]; Bl[nt2*2+1][0]=t[2]; Bl[nt2*2+1][1]=t[3];
            }
            #pragma unroll
            for (int fm = 0; fm < 6; fm++) {
                int mrow = wm * 96 + fm * 16 + (g & 1) * 8 + r;
                int kcol = kk + (g >> 1) * 8;
                uint32_t Ah[4], Al[4];
                ldm4(Ah, sptr(Whi + mrow * WS + kcol));
                ldm4(Al, sptr(Wlo + mrow * WS + kcol));
                #pragma unroll
                for (int fn = 0; fn < 4; fn++) {
                    mma16816(acc[fm][fn], Ah, Bh[fn]);
                    mma16816(acc[fm][fn], Ah, Bl[fn]);
                    mma16816(acc[fm][fn], Al, Bh[fn]);
                }
            }
        }
        __syncthreads();
    }

    // ---- v rows (m 128..191, wm==1 frags 2..5): bias, split, -> global ----
    if (wm == 1) {
        #pragma unroll
        for (int fm = 2; fm < 6; fm++) {
            int cb0 = (fm - 2) * 16 + q_r;
            float bv0 = bv[cb0], bv8 = bv[cb0 + 8];
            #pragma unroll
            for (int fn = 0; fn < 4; fn++) {
                int n = n_base + wn * 32 + fn * 8 + q_c;
                float v0 = acc[fm][fn][0] + bv0, v1 = acc[fm][fn][1] + bv0;
                float v2 = acc[fm][fn][2] + bv8, v3 = acc[fm][fn][3] + bv8;
                __nv_bfloat16 h0, l0, h1, l1, h2, l2, h3, l3;
                split2(v0, h0, l0); split2(v1, h1, l1);
                split2(v2, h2, l2); split2(v3, h3, l3);
                size_t o0 = ((size_t)b * CB + cb0) * NN + n;
                size_t o8 = o0 + (size_t)8 * NN;
                *reinterpret_cast<__nv_bfloat162*>(g_v_hi + o0) = __nv_bfloat162(h0, h1);
                *reinterpret_cast<__nv_bfloat162*>(g_v_lo + o0) = __nv_bfloat162(l0, l1);
                *reinterpret_cast<__nv_bfloat162*>(g_v_hi + o8) = __nv_bfloat162(h2, h3);
                *reinterpret_cast<__nv_bfloat162*>(g_v_lo + o8) = __nv_bfloat162(l2, l3);
            }
        }
    }

    // ---- logits: two n-halves; q,k re-split to bf16 hi/lo, mma accumulate ----
    float lacc[4][4];
    #pragma unroll
    for (int i = 0; i < 4; i++)
        #pragma unroll
        for (int j = 0; j < 4; j++) lacc[i][j] = 0.f;
    const int wml = wid >> 1, wnl = wid & 1;     // logits warp grid 4m x 2n

    #pragma unroll
    for (int p = 0; p < 2; p++) {
        __syncthreads();   // prior smem consumers done
        if ((wn >> 1) == p) {   // this warp's n-slice belongs to half p
            #pragma unroll
            for (int fm = 0; fm < 6; fm++) {
                int m0 = wm * 96 + fm * 16 + q_r;
                if (m0 < 128) {
                    bool isq = (m0 < 64);
                    int r0 = isq ? m0 : (m0 - 64);
                    float bb0 = isq ? bq[m0] : bk[m0 - 64];
                    float bb8 = isq ? bq[m0 + 8] : bk[m0 - 56];
                    __nv_bfloat16* Phi = isq ? Qhi : Khi;
                    __nv_bfloat16* Plo = isq ? Qlo : Klo;
                    #pragma unroll
                    for (int fn = 0; fn < 4; fn++) {
                        int col = wn * 32 + fn * 8 + q_c - p * 64;
                        float v0 = acc[fm][fn][0] + bb0, v1 = acc[fm][fn][1] + bb0;
                        float v2 = acc[fm][fn][2] + bb8, v3 = acc[fm][fn][3] + bb8;
                        __nv_bfloat16 h0, l0, h1, l1, h2, l2, h3, l3;
                        split2(v0, h0, l0); split2(v1, h1, l1);
                        split2(v2, h2, l2); split2(v3, h3, l3);
                        *reinterpret_cast<__nv_bfloat162*>(Phi + r0 * QS + col)       = __nv_bfloat162(h0, h1);
                        *reinterpret_cast<__nv_bfloat162*>(Plo + r0 * QS + col)       = __nv_bfloat162(l0, l1);
                        *reinterpret_cast<__nv_bfloat162*>(Phi + (r0 + 8) * QS + col) = __nv_bfloat162(h2, h3);
                        *reinterpret_cast<__nv_bfloat162*>(Plo + (r0 + 8) * QS + col) = __nv_bfloat162(l2, l3);
                    }
                }
            }
        }
        __syncthreads();
        // logits mma over this 64-wide half (4 k16 steps)
        #pragma unroll
        for (int ks = 0; ks < 4; ks++) {
            const int kk = ks * 16;
            uint32_t Ah[4], Al[4];
            {
                int row = wml * 16 + (g & 1) * 8 + r;
                int col = kk + (g >> 1) * 8;
                ldm4(Ah, sptr(Qhi + row * QS + col));
                ldm4(Al, sptr(Qlo + row * QS + col));
            }
            #pragma unroll
            for (int dt = 0; dt < 2; dt++) {
                int drow = wnl * 32 + dt * 16 + (g >> 1) * 8 + r;
                int dcol = kk + (g & 1) * 8;
                uint32_t Bh_[4], Bl_[4];
                ldm4(Bh_, sptr(Khi + drow * QS + dcol));
                ldm4(Bl_, sptr(Klo + drow * QS + dcol));
                mma16816(lacc[dt*2],     Ah, Bh_ + 0);
                mma16816(lacc[dt*2],     Ah, Bl_ + 0);
                mma16816(lacc[dt*2],     Al, Bh_ + 0);
                mma16816(lacc[dt*2 + 1], Ah, Bh_ + 2);
                mma16816(lacc[dt*2 + 1], Ah, Bl_ + 2);
                mma16816(lacc[dt*2 + 1], Al, Bh_ + 2);
            }
        }
    }

    // ---- write logits partial [64,64] ----
    float* lp = g_lp + (size_t)(b * NT + ntile) * (CB * CB);
    #pragma unroll
    for (int df = 0; df < 4; df++) {
        int cr = wml * 16 + q_r;
        int dc = wnl * 32 + df * 8 + q_c;
        lp[cr * CB + dc]           = lacc[df][0];
        lp[cr * CB + dc + 1]       = lacc[df][1];
        lp[(cr + 8) * CB + dc]     = lacc[df][2];
        lp[(cr + 8) * CB + dc + 1] = lacc[df][3];
    }
}

// ---------------------------------------------------------------------------
// Kernel 2a: parallel reduction of the 32 logits partials.
// grid (16, 16), block 256: each block reduces 256 of the 4096 elems/batch.
// ---------------------------------------------------------------------------
__global__ __launch_bounds__(256) void reduce_lp_kernel()
{
    const int b = blockIdx.x;
    const int idx = blockIdx.y * 256 + threadIdx.x;   // 0..4095
    const float* base = g_lp + (size_t)b * NT * (CB * CB) + idx;
    float s = 0.f;
    #pragma unroll 8
    for (int t = 0; t < NT; t++)
        s += base[(size_t)t * (CB * CB)];
    g_logits[(size_t)b * (CB * CB) + idx] = s;
}

// ---------------------------------------------------------------------------
// Kernel 2b: softmax(rows) -> M = gamma * (w_o @ attn) -> bf16 hi/lo.
// grid (16, 4), block 256.
// ---------------------------------------------------------------------------
__global__ __launch_bounds__(256) void softmax_m_kernel(
    const float* __restrict__ w_o, const float* __restrict__ gamma)
{
    __shared__ float L[CB * CB];
    const int b = blockIdx.x, cbase = blockIdx.y * 128, tid = threadIdx.x;

    #pragma unroll
    for (int t = 0; t < 16; t++) {
        int idx = tid + 256 * t;
        L[idx] = g_logits[(size_t)b * (CB * CB) + idx];
    }
    __syncthreads();

    if (tid < CB) {
        float* row = &L[tid * CB];
        float mx = row[0];
        #pragma unroll
        for (int d = 1; d < CB; d++) mx = fmaxf(mx, row[d]);
        float sum = 0.f;
        #pragma unroll
        for (int d = 0; d < CB; d++) { float e = expf(row[d] - mx); row[d] = e; sum += e; }
        float inv = 1.f / sum;
        #pragma unroll
        for (int d = 0; d < CB; d++) row[d] *= inv;
    }
    __syncthreads();

    const float gm = gamma[0];
    for (int o = tid; o < 128 * CB; o += 256) {
        int c = cbase + (o >> 6), d = o & 63;
        float sum = 0.f;
        #pragma unroll
        for (int e = 0; e < CB; e++)
            sum = fmaf(w_o[c * CB + e], L[e * CB + d], sum);
        float mval = gm * sum;
        __nv_bfloat16 h, l;
        split2(mval, h, l);
        size_t off = ((size_t)b * CC + c) * CB + d;
        g_M_hi[off] = h;
        g_M_lo[off] = l;
    }
}

// ---------------------------------------------------------------------------
// Kernel 3: out = M@v (bf16x3 mma) + gamma*b_o + x.  EXACT R6 (87.6us).
// grid (32, 4, 16), block 256, 2 CTAs/SM.  Smem-staged coalesced epilogue.
// ---------------------------------------------------------------------------
__global__ __launch_bounds__(256, 2) void out_kernel(
    const float* __restrict__ x,
    const float* __restrict__ b_o, const float* __restrict__ gamma,
    float* __restrict__ out)
{
    __shared__ __align__(16) __nv_bfloat16 smem[18944];
    __nv_bfloat16* Mhi = smem;            // [128][40]
    __nv_bfloat16* Mlo = smem + 5120;
    __nv_bfloat16* Vhi = smem + 10240;    // [32][136]
    __nv_bfloat16* Vlo = smem + 14592;

    const int b = blockIdx.z, cb0 = blockIdx.y * 128, n_base = blockIdx.x * 128;
    const int tid = threadIdx.x, lane = tid & 31, wid = tid >> 5;
    const int wm = wid >> 1, wn = wid & 1;
    const int g = lane >> 3, r = lane & 7;
    const int q_r = lane >> 2, q_c = (lane & 3) * 2;

    float acc[2][8][4];
    #pragma unroll
    for (int i = 0; i < 2; i++)
        #pragma unroll
        for (int j = 0; j < 8; j++)
            #pragma unroll
            for (int e = 0; e < 4; e++) acc[i][j][e] = 0.f;

    #pragma unroll
    for (int ec = 0; ec < 2; ec++) {
        const int e0 = ec * 32;
        #pragma unroll
        for (int i = 0; i < 8; i++) {
            int idx = i * 256 + tid;
            int c = idx >> 4, e2 = (idx & 15) * 2;
            size_t off = ((size_t)b * CC + cb0 + c) * CB + e0 + e2;
            *reinterpret_cast<__nv_bfloat162*>(Mhi + c * MS + e2) =
                *reinterpret_cast<const __nv_bfloat162*>(g_M_hi + off);
            *reinterpret_cast<__nv_bfloat162*>(Mlo + c * MS + e2) =
                *reinterpret_cast<const __nv_bfloat162*>(g_M_lo + off);
        }
        #pragma unroll
        for (int i = 0; i < 4; i++) {
            int idx = i * 256 + tid;
            int e = idx >> 5, n4 = (idx & 31) * 4;
            size_t off = ((size_t)b * CB + e0 + e) * NN + n_base + n4;
            *reinterpret_cast<uint2*>(Vhi + e * XS + n4) =
                *reinterpret_cast<const uint2*>(g_v_hi + off);
            *reinterpret_cast<uint2*>(Vlo + e * XS + n4) =
                *reinterpret_cast<const uint2*>(g_v_lo + off);
        }
        __syncthreads();

        #pragma unroll
        for (int ks = 0; ks < 2; ks++) {
            const int kk = ks * 16;
            uint32_t Ah[2][4], Al[2][4];
            #pragma unroll
            for (int fm = 0; fm < 2; fm++) {
                int mrow = wm * 32 + fm * 16 + (g & 1) * 8 + r;
                int kcol = kk + (g >> 1) * 8;
                ldm4(Ah[fm], sptr(Mhi + mrow * MS + kcol));
                ldm4(Al[fm], sptr(Mlo + mrow * MS + kcol));
            }
            #pragma unroll
            for (int h = 0; h < 2; h++) {
                uint32_t Bh[4][2], Bl[4][2];
                #pragma unroll
                for (int nt = 0; nt < 2; nt++) {
                    int row = kk + (g & 1) * 8 + r;
                    int col = wn * 64 + h * 32 + nt * 16 + (g >> 1) * 8;
                    uint32_t t[4];
                    ldm4t(t, sptr(Vhi + row * XS + col));
                    Bh[nt*2][0]=t[0]; Bh[nt*2][1]=t[1]; Bh[nt*2+1][0]=t[2]; Bh[nt*2+1][1]=t[3];
                    ldm4t(t, sptr(Vlo + row * XS + col));
                    Bl[nt*2][0]=t[0]; Bl[nt*2][1]=t[1]; Bl[nt*2+1][0]=t[2]; Bl[nt*2+1][1]=t[3];
                }
                #pragma unroll
                for (int fm = 0; fm < 2; fm++) {
                    #pragma unroll
                    for (int fn4 = 0; fn4 < 4; fn4++) {
                        float* c = acc[fm][h * 4 + fn4];
                        mma16816(c, Ah[fm], Bh[fn4]);
                        mma16816(c, Ah[fm], Bl[fn4]);
                        mma16816(c, Al[fm], Bh[fn4]);
                    }
                }
            }
        }
        __syncthreads();
    }

    // ---- smem-staged coalesced epilogue: two chunks of 64 rows ----
    float* S = reinterpret_cast<float*>(smem);   // [64][136] fp32
    const float gm = gamma[0];
    #pragma unroll
    for (int cc = 0; cc < 2; cc++) {
        if ((wm >> 1) == cc) {
            #pragma unroll
            for (int fm = 0; fm < 2; fm++) {
                int sr = (wm & 1) * 32 + fm * 16 + q_r;
                #pragma unroll
                for (int fn = 0; fn < 8; fn++) {
                    int sc = wn * 64 + fn * 8 + q_c;
                    *reinterpret_cast<float2*>(&S[sr * 136 + sc]) =
                        make_float2(acc[fm][fn][0], acc[fm][fn][1]);
                    *reinterpret_cast<float2*>(&S[(sr + 8) * 136 + sc]) =
                        make_float2(acc[fm][fn][2], acc[fm][fn][3]);
                }
            }
        }
        __syncthreads();
        #pragma unroll
        for (int i = 0; i < 8; i++) {
            int idx = i * 256 + tid;
            int row = idx >> 5, n4 = (idx & 31) * 4;
            int c = cb0 + cc * 64 + row;
            float gb = gm * b_o[c];
            size_t off = ((size_t)b * CC + c) * NN + n_base + n4;
            float4 xv = *reinterpret_cast<const float4*>(x + off);
            float4 sv = *reinterpret_cast<const float4*>(&S[row * 136 + n4]);
            float4 rv = {sv.x + gb + xv.x, sv.y + gb + xv.y,
                         sv.z + gb + xv.z, sv.w + gb + xv.w};
            *reinterpret_cast<float4*>(out + off) = rv;
        }
        __syncthreads();
    }
}

// ---------------------------------------------------------------------------
// Launch
// ---------------------------------------------------------------------------
extern "C" void kernel_launch(void* const* d_in, const int* in_sizes, int n_in,
                              void* d_out, int out_size)
{
    const float* x     = (const float*)d_in[0];
    const float* w_q   = (const float*)d_in[1];
    const float* b_q   = (const float*)d_in[2];
    const float* w_k   = (const float*)d_in[3];
    const float* b_k   = (const float*)d_in[4];
    const float* w_v   = (const float*)d_in[5];
    const float* b_v   = (const float*)d_in[6];
    const float* w_o   = (const float*)d_in[7];
    const float* b_o   = (const float*)d_in[8];
    const float* gamma = (const float*)d_in[9];
    float* out = (float*)d_out;

    qkv_logits_kernel<<<dim3(NT, BB), 256>>>(x, w_q, b_q, w_k, b_k, w_v, b_v);
    reduce_lp_kernel<<<dim3(BB, 16), 256>>>();
    softmax_m_kernel<<<dim3(BB, 4), 256>>>(w_o, gamma);
    out_kernel<<<dim3(NN / 128, CC / 128, BB), 256>>>(x, b_o, gamma, out);
}

// round 17
// speedup vs baseline: 1.0773x; 1.0773x over previous
#include <cuda_runtime.h>
#include <cuda_bf16.h>
#include <math.h>
#include <stdint.h>

// Problem constants
#define BB 16
#define CC 512
#define CB 64
#define NN 4096
#define NT 64    // n-tiles of 64 per batch

// ---------------------------------------------------------------------------
// Scratch (static __device__ arrays — no runtime allocation)
// ---------------------------------------------------------------------------
__device__ __align__(16) __nv_bfloat16 g_v_hi[BB * CB * NN];   // 8 MB
__device__ __align__(16) __nv_bfloat16 g_v_lo[BB * CB * NN];   // 8 MB
__device__ float g_lp[BB * NT * CB * CB];                      // 16 MB
__device__ float g_logits[BB * CB * CB];                       // 256 KB
__device__ __align__(16) __nv_bfloat16 g_M_hi[BB * CC * CB];   // 1 MB
__device__ __align__(16) __nv_bfloat16 g_M_lo[BB * CC * CB];   // 1 MB

// ---------------------------------------------------------------------------
// MMA helpers (warp mma, bf16 in / fp32 accum)
// ---------------------------------------------------------------------------
__device__ __forceinline__ uint32_t sptr(const void* p) {
    return (uint32_t)__cvta_generic_to_shared(p);
}
__device__ __forceinline__ void ldm4(uint32_t* r, uint32_t a) {
    asm volatile("ldmatrix.sync.aligned.m8n8.x4.shared.b16 {%0,%1,%2,%3}, [%4];"
        : "=r"(r[0]), "=r"(r[1]), "=r"(r[2]), "=r"(r[3]) : "r"(a));
}
__device__ __forceinline__ void ldm4t(uint32_t* r, uint32_t a) {
    asm volatile("ldmatrix.sync.aligned.m8n8.x4.trans.shared.b16 {%0,%1,%2,%3}, [%4];"
        : "=r"(r[0]), "=r"(r[1]), "=r"(r[2]), "=r"(r[3]) : "r"(a));
}
__device__ __forceinline__ void mma16816(float* c, const uint32_t* a, const uint32_t* b) {
    asm volatile("mma.sync.aligned.m16n8k16.row.col.f32.bf16.bf16.f32 "
        "{%0,%1,%2,%3}, {%4,%5,%6,%7}, {%8,%9}, {%0,%1,%2,%3};"
        : "+f"(c[0]), "+f"(c[1]), "+f"(c[2]), "+f"(c[3])
        : "r"(a[0]), "r"(a[1]), "r"(a[2]), "r"(a[3]), "r"(b[0]), "r"(b[1]));
}
__device__ __forceinline__ void split2(float v, __nv_bfloat16& h, __nv_bfloat16& l) {
    h = __float2bfloat16_rn(v);
    l = __float2bfloat16_rn(v - __bfloat162float(h));
}

#define WS 40     // W smem row stride (bf16)
#define X2 72     // qkv X smem row stride (bf16), 64-n tile
#define XS 136    // out-kernel V smem row stride
#define QS 72     // Q/K smem row stride (bf16)
#define MS 40     // out-kernel M smem row stride

// ---------------------------------------------------------------------------
// Kernel 1: fused QKV projection (bf16x3 mma) + logits partial (bf16x3 mma).
// grid (64, 16), block 256 (8 warps), 2 CTAs/SM.
// Block tile P[192 m x 64 n]; warp grid 2m x 4n -> warp tile 96 x 16.
// The two co-resident CTAs interleave load/split and mma phases, hiding
// global latency without intra-CTA pipelining.
// ---------------------------------------------------------------------------
__global__ __launch_bounds__(256, 2) void qkv_logits_kernel(
    const float* __restrict__ x,
    const float* __restrict__ wq, const float* __restrict__ bq,
    const float* __restrict__ wk, const float* __restrict__ bk,
    const float* __restrict__ wv, const float* __restrict__ bv)
{
    __shared__ __align__(16) __nv_bfloat16 smem[19968];  // 39936 B
    // phase 1 layout
    __nv_bfloat16* Whi = smem;            // [192][40]
    __nv_bfloat16* Wlo = smem + 7680;
    __nv_bfloat16* Xhi = smem + 15360;    // [32][72]
    __nv_bfloat16* Xlo = smem + 17664;
    // phase 2 layout (union; phase 1 data dead by then)
    __nv_bfloat16* Qhi = smem;            // [64][72] x4
    __nv_bfloat16* Qlo = smem + 4608;
    __nv_bfloat16* Khi = smem + 9216;
    __nv_bfloat16* Klo = smem + 13824;

    const int b = blockIdx.y, ntile = blockIdx.x;
    const int n_base = ntile * 64;
    const int tid = threadIdx.x, lane = tid & 31, wid = tid >> 5;
    const int wm = wid >> 2, wn = wid & 3;     // warp grid 2m x 4n
    const int g = lane >> 3, r = lane & 7;     // ldmatrix addressing
    const int q_r = lane >> 2, q_c = (lane & 3) * 2;  // C-fragment coords

    const float* xb = x + (size_t)b * CC * NN;

    float acc[6][2][4];
    #pragma unroll
    for (int i = 0; i < 6; i++)
        #pragma unroll
        for (int j = 0; j < 2; j++)
            #pragma unroll
            for (int e = 0; e < 4; e++) acc[i][j][e] = 0.f;

    for (int kc = 0; kc < 16; kc++) {
        const int k0 = kc * 32;
        // ---- load & split W chunk [192 m][32 k] ----
        #pragma unroll
        for (int i = 0; i < 6; i++) {
            int idx4 = i * 256 + tid;            // 0..1535
            int m = idx4 >> 3, kq = (idx4 & 7) * 4;
            const float* src;
            if (m < 64)       src = wq + m * CC;
            else if (m < 128) src = wk + (m - 64) * CC;
            else              src = wv + (m - 128) * CC;
            float4 v = *reinterpret_cast<const float4*>(src + k0 + kq);
            __nv_bfloat16 h0, l0, h1, l1, h2, l2, h3, l3;
            split2(v.x, h0, l0); split2(v.y, h1, l1);
            split2(v.z, h2, l2); split2(v.w, h3, l3);
            __nv_bfloat16* dh = Whi + m * WS + kq;
            __nv_bfloat16* dl = Wlo + m * WS + kq;
            *reinterpret_cast<__nv_bfloat162*>(dh)     = __nv_bfloat162(h0, h1);
            *reinterpret_cast<__nv_bfloat162*>(dh + 2) = __nv_bfloat162(h2, h3);
            *reinterpret_cast<__nv_bfloat162*>(dl)     = __nv_bfloat162(l0, l1);
            *reinterpret_cast<__nv_bfloat162*>(dl + 2) = __nv_bfloat162(l2, l3);
        }
        // ---- load & split X chunk [32 k][64 n] ----
        #pragma unroll
        for (int i = 0; i < 2; i++) {
            int idx4 = i * 256 + tid;            // 0..511
            int k = idx4 >> 4, n4 = (idx4 & 15) * 4;
            float4 v = *reinterpret_cast<const float4*>(
                xb + (size_t)(k0 + k) * NN + n_base + n4);
            __nv_bfloat16 h0, l0, h1, l1, h2, l2, h3, l3;
            split2(v.x, h0, l0); split2(v.y, h1, l1);
            split2(v.z, h2, l2); split2(v.w, h3, l3);
            __nv_bfloat16* dh = Xhi + k * X2 + n4;
            __nv_bfloat16* dl = Xlo + k * X2 + n4;
            *reinterpret_cast<__nv_bfloat162*>(dh)     = __nv_bfloat162(h0, h1);
            *reinterpret_cast<__nv_bfloat162*>(dh + 2) = __nv_bfloat162(h2, h3);
            *reinterpret_cast<__nv_bfloat162*>(dl)     = __nv_bfloat162(l0, l1);
            *reinterpret_cast<__nv_bfloat162*>(dl + 2) = __nv_bfloat162(l2, l3);
        }
        __syncthreads();

        #pragma unroll
        for (int ks = 0; ks < 2; ks++) {
            const int kk = ks * 16;
            uint32_t Bh[2][2], Bl[2][2];
            {
                int row = kk + (g & 1) * 8 + r;
                int col = wn * 16 + (g >> 1) * 8;
                uint32_t t[4];
                ldm4t(t, sptr(Xhi + row * X2 + col));
                Bh[0][0] = t[0]; Bh[0][1] = t[1]; Bh[1][0] = t[2]; Bh[1][1] = t[3];
                ldm4t(t, sptr(Xlo + row * X2 + col));
                Bl[0][0] = t[0]; Bl[0][1] = t[1]; Bl[1][0] = t[2]; Bl[1][1] = t[3];
            }
            #pragma unroll
            for (int fm = 0; fm < 6; fm++) {
                int mrow = wm * 96 + fm * 16 + (g & 1) * 8 + r;
                int kcol = kk + (g >> 1) * 8;
                uint32_t Ah[4], Al[4];
                ldm4(Ah, sptr(Whi + mrow * WS + kcol));
                ldm4(Al, sptr(Wlo + mrow * WS + kcol));
                #pragma unroll
                for (int fn = 0; fn < 2; fn++) {
                    mma16816(acc[fm][fn], Ah, Bh[fn]);
                    mma16816(acc[fm][fn], Ah, Bl[fn]);
                    mma16816(acc[fm][fn], Al, Bh[fn]);
                }
            }
        }
        __syncthreads();
    }

    // ---- v rows (m 128..191, wm==1 frags 2..5): bias, split, -> global ----
    if (wm == 1) {
        #pragma unroll
        for (int fm = 2; fm < 6; fm++) {
            int cb0 = (fm - 2) * 16 + q_r;
            float bv0 = bv[cb0], bv8 = bv[cb0 + 8];
            #pragma unroll
            for (int fn = 0; fn < 2; fn++) {
                int n = n_base + wn * 16 + fn * 8 + q_c;
                float v0 = acc[fm][fn][0] + bv0, v1 = acc[fm][fn][1] + bv0;
                float v2 = acc[fm][fn][2] + bv8, v3 = acc[fm][fn][3] + bv8;
                __nv_bfloat16 h0, l0, h1, l1, h2, l2, h3, l3;
                split2(v0, h0, l0); split2(v1, h1, l1);
                split2(v2, h2, l2); split2(v3, h3, l3);
                size_t o0 = ((size_t)b * CB + cb0) * NN + n;
                size_t o8 = o0 + (size_t)8 * NN;
                *reinterpret_cast<__nv_bfloat162*>(g_v_hi + o0) = __nv_bfloat162(h0, h1);
                *reinterpret_cast<__nv_bfloat162*>(g_v_lo + o0) = __nv_bfloat162(l0, l1);
                *reinterpret_cast<__nv_bfloat162*>(g_v_hi + o8) = __nv_bfloat162(h2, h3);
                *reinterpret_cast<__nv_bfloat162*>(g_v_lo + o8) = __nv_bfloat162(l2, l3);
            }
        }
    }

    // ---- logits: single 64-n tile; q,k re-split to bf16 hi/lo, mma ----
    __syncthreads();   // phase-1 smem consumers done
    #pragma unroll
    for (int fm = 0; fm < 6; fm++) {
        int m0f = wm * 96 + fm * 16;
        if (m0f < 128) {
            int m0 = m0f + q_r;
            bool isq = (m0f < 64);
            int r0 = isq ? m0 : (m0 - 64);
            float bb0 = isq ? bq[m0] : bk[m0 - 64];
            float bb8 = isq ? bq[m0 + 8] : bk[m0 - 56];
            __nv_bfloat16* Phi = isq ? Qhi : Khi;
            __nv_bfloat16* Plo = isq ? Qlo : Klo;
            #pragma unroll
            for (int fn = 0; fn < 2; fn++) {
                int col = wn * 16 + fn * 8 + q_c;
                float v0 = acc[fm][fn][0] + bb0, v1 = acc[fm][fn][1] + bb0;
                float v2 = acc[fm][fn][2] + bb8, v3 = acc[fm][fn][3] + bb8;
                __nv_bfloat16 h0, l0, h1, l1, h2, l2, h3, l3;
                split2(v0, h0, l0); split2(v1, h1, l1);
                split2(v2, h2, l2); split2(v3, h3, l3);
                *reinterpret_cast<__nv_bfloat162*>(Phi + r0 * QS + col)       = __nv_bfloat162(h0, h1);
                *reinterpret_cast<__nv_bfloat162*>(Plo + r0 * QS + col)       = __nv_bfloat162(l0, l1);
                *reinterpret_cast<__nv_bfloat162*>(Phi + (r0 + 8) * QS + col) = __nv_bfloat162(h2, h3);
                *reinterpret_cast<__nv_bfloat162*>(Plo + (r0 + 8) * QS + col) = __nv_bfloat162(l2, l3);
            }
        }
    }
    __syncthreads();

    float lacc[4][4];
    #pragma unroll
    for (int i = 0; i < 4; i++)
        #pragma unroll
        for (int j = 0; j < 4; j++) lacc[i][j] = 0.f;
    const int wml = wid >> 1, wnl = wid & 1;     // logits warp grid 4m x 2n

    #pragma unroll
    for (int ks = 0; ks < 4; ks++) {
        const int kk = ks * 16;
        uint32_t Ah[4], Al[4];
        {
            int row = wml * 16 + (g & 1) * 8 + r;
            int col = kk + (g >> 1) * 8;
            ldm4(Ah, sptr(Qhi + row * QS + col));
            ldm4(Al, sptr(Qlo + row * QS + col));
        }
        #pragma unroll
        for (int dt = 0; dt < 2; dt++) {
            int drow = wnl * 32 + dt * 16 + (g >> 1) * 8 + r;
            int dcol = kk + (g & 1) * 8;
            uint32_t Bh_[4], Bl_[4];
            ldm4(Bh_, sptr(Khi + drow * QS + dcol));
            ldm4(Bl_, sptr(Klo + drow * QS + dcol));
            mma16816(lacc[dt*2],     Ah, Bh_ + 0);
            mma16816(lacc[dt*2],     Ah, Bl_ + 0);
            mma16816(lacc[dt*2],     Al, Bh_ + 0);
            mma16816(lacc[dt*2 + 1], Ah, Bh_ + 2);
            mma16816(lacc[dt*2 + 1], Ah, Bl_ + 2);
            mma16816(lacc[dt*2 + 1], Al, Bh_ + 2);
        }
    }

    // ---- write logits partial [64,64] ----
    float* lp = g_lp + (size_t)(b * NT + ntile) * (CB * CB);
    #pragma unroll
    for (int df = 0; df < 4; df++) {
        int cr = wml * 16 + q_r;
        int dc = wnl * 32 + df * 8 + q_c;
        lp[cr * CB + dc]           = lacc[df][0];
        lp[cr * CB + dc + 1]       = lacc[df][1];
        lp[(cr + 8) * CB + dc]     = lacc[df][2];
        lp[(cr + 8) * CB + dc + 1] = lacc[df][3];
    }
}

// ---------------------------------------------------------------------------
// Kernel 2a: parallel reduction of the 64 logits partials.
// grid (16, 16), block 256.
// ---------------------------------------------------------------------------
__global__ __launch_bounds__(256) void reduce_lp_kernel()
{
    const int b = blockIdx.x;
    const int idx = blockIdx.y * 256 + threadIdx.x;   // 0..4095
    const float* base = g_lp + (size_t)b * NT * (CB * CB) + idx;
    float s = 0.f;
    #pragma unroll 8
    for (int t = 0; t < NT; t++)
        s += base[(size_t)t * (CB * CB)];
    g_logits[(size_t)b * (CB * CB) + idx] = s;
}

// ---------------------------------------------------------------------------
// Kernel 2b: softmax(rows) -> M = gamma * (w_o @ attn) -> bf16 hi/lo.
// grid (16, 4), block 256.  (unchanged)
// ---------------------------------------------------------------------------
__global__ __launch_bounds__(256) void softmax_m_kernel(
    const float* __restrict__ w_o, const float* __restrict__ gamma)
{
    __shared__ float L[CB * CB];
    const int b = blockIdx.x, cbase = blockIdx.y * 128, tid = threadIdx.x;

    #pragma unroll
    for (int t = 0; t < 16; t++) {
        int idx = tid + 256 * t;
        L[idx] = g_logits[(size_t)b * (CB * CB) + idx];
    }
    __syncthreads();

    if (tid < CB) {
        float* row = &L[tid * CB];
        float mx = row[0];
        #pragma unroll
        for (int d = 1; d < CB; d++) mx = fmaxf(mx, row[d]);
        float sum = 0.f;
        #pragma unroll
        for (int d = 0; d < CB; d++) { float e = expf(row[d] - mx); row[d] = e; sum += e; }
        float inv = 1.f / sum;
        #pragma unroll
        for (int d = 0; d < CB; d++) row[d] *= inv;
    }
    __syncthreads();

    const float gm = gamma[0];
    for (int o = tid; o < 128 * CB; o += 256) {
        int c = cbase + (o >> 6), d = o & 63;
        float sum = 0.f;
        #pragma unroll
        for (int e = 0; e < CB; e++)
            sum = fmaf(w_o[c * CB + e], L[e * CB + d], sum);
        float mval = gm * sum;
        __nv_bfloat16 h, l;
        split2(mval, h, l);
        size_t off = ((size_t)b * CC + c) * CB + d;
        g_M_hi[off] = h;
        g_M_lo[off] = l;
    }
}

// ---------------------------------------------------------------------------
// Kernel 3: out = M@v (bf16x3 mma) + gamma*b_o + x.  (unchanged, 87.6us)
// grid (32, 4, 16), block 256, 2 CTAs/SM.  Smem-staged coalesced epilogue.
// ---------------------------------------------------------------------------
__global__ __launch_bounds__(256, 2) void out_kernel(
    const float* __restrict__ x,
    const float* __restrict__ b_o, const float* __restrict__ gamma,
    float* __restrict__ out)
{
    __shared__ __align__(16) __nv_bfloat16 smem[18944];
    __nv_bfloat16* Mhi = smem;            // [128][40]
    __nv_bfloat16* Mlo = smem + 5120;
    __nv_bfloat16* Vhi = smem + 10240;    // [32][136]
    __nv_bfloat16* Vlo = smem + 14592;

    const int b = blockIdx.z, cb0 = blockIdx.y * 128, n_base = blockIdx.x * 128;
    const int tid = threadIdx.x, lane = tid & 31, wid = tid >> 5;
    const int wm = wid >> 1, wn = wid & 1;
    const int g = lane >> 3, r = lane & 7;
    const int q_r = lane >> 2, q_c = (lane & 3) * 2;

    float acc[2][8][4];
    #pragma unroll
    for (int i = 0; i < 2; i++)
        #pragma unroll
        for (int j = 0; j < 8; j++)
            #pragma unroll
            for (int e = 0; e < 4; e++) acc[i][j][e] = 0.f;

    #pragma unroll
    for (int ec = 0; ec < 2; ec++) {
        const int e0 = ec * 32;
        #pragma unroll
        for (int i = 0; i < 8; i++) {
            int idx = i * 256 + tid;
            int c = idx >> 4, e2 = (idx & 15) * 2;
            size_t off = ((size_t)b * CC + cb0 + c) * CB + e0 + e2;
            *reinterpret_cast<__nv_bfloat162*>(Mhi + c * MS + e2) =
                *reinterpret_cast<const __nv_bfloat162*>(g_M_hi + off);
            *reinterpret_cast<__nv_bfloat162*>(Mlo + c * MS + e2) =
                *reinterpret_cast<const __nv_bfloat162*>(g_M_lo + off);
        }
        #pragma unroll
        for (int i = 0; i < 4; i++) {
            int idx = i * 256 + tid;
            int e = idx >> 5, n4 = (idx & 31) * 4;
            size_t off = ((size_t)b * CB + e0 + e) * NN + n_base + n4;
            *reinterpret_cast<uint2*>(Vhi + e * XS + n4) =
                *reinterpret_cast<const uint2*>(g_v_hi + off);
            *reinterpret_cast<uint2*>(Vlo + e * XS + n4) =
                *reinterpret_cast<const uint2*>(g_v_lo + off);
        }
        __syncthreads();

        #pragma unroll
        for (int ks = 0; ks < 2; ks++) {
            const int kk = ks * 16;
            uint32_t Ah[2][4], Al[2][4];
            #pragma unroll
            for (int fm = 0; fm < 2; fm++) {
                int mrow = wm * 32 + fm * 16 + (g & 1) * 8 + r;
                int kcol = kk + (g >> 1) * 8;
                ldm4(Ah[fm], sptr(Mhi + mrow * MS + kcol));
                ldm4(Al[fm], sptr(Mlo + mrow * MS + kcol));
            }
            #pragma unroll
            for (int h = 0; h < 2; h++) {
                uint32_t Bh[4][2], Bl[4][2];
                #pragma unroll
                for (int nt = 0; nt < 2; nt++) {
                    int row = kk + (g & 1) * 8 + r;
                    int col = wn * 64 + h * 32 + nt * 16 + (g >> 1) * 8;
                    uint32_t t[4];
                    ldm4t(t, sptr(Vhi + row * XS + col));
                    Bh[nt*2][0]=t[0]; Bh[nt*2][1]=t[1]; Bh[nt*2+1][0]=t[2]; Bh[nt*2+1][1]=t[3];
                    ldm4t(t, sptr(Vlo + row * XS + col));
                    Bl[nt*2][0]=t[0]; Bl[nt*2][1]=t[1]; Bl[nt*2+1][0]=t[2]; Bl[nt*2+1][1]=t[3];
                }
                #pragma unroll
                for (int fm = 0; fm < 2; fm++) {
                    #pragma unroll
                    for (int fn4 = 0; fn4 < 4; fn4++) {
                        float* c = acc[fm][h * 4 + fn4];
                        mma16816(c, Ah[fm], Bh[fn4]);
                        mma16816(c, Ah[fm], Bl[fn4]);
                        mma16816(c, Al[fm], Bh[fn4]);
                    }
                }
            }
        }
        __syncthreads();
    }

    float* S = reinterpret_cast<float*>(smem);
    const float gm = gamma[0];
    #pragma unroll
    for (int cc = 0; cc < 2; cc++) {
        if ((wm >> 1) == cc) {
            #pragma unroll
            for (int fm = 0; fm < 2; fm++) {
                int sr = (wm & 1) * 32 + fm * 16 + q_r;
                #pragma unroll
                for (int fn = 0; fn < 8; fn++) {
                    int sc = wn * 64 + fn * 8 + q_c;
                    *reinterpret_cast<float2*>(&S[sr * 136 + sc]) =
                        make_float2(acc[fm][fn][0], acc[fm][fn][1]);
                    *reinterpret_cast<float2*>(&S[(sr + 8) * 136 + sc]) =
                        make_float2(acc[fm][fn][2], acc[fm][fn][3]);
                }
            }
        }
        __syncthreads();
        #pragma unroll
        for (int i = 0; i < 8; i++) {
            int idx = i * 256 + tid;
            int row = idx >> 5, n4 = (idx & 31) * 4;
            int c = cb0 + cc * 64 + row;
            float gb = gm * b_o[c];
            size_t off = ((size_t)b * CC + c) * NN + n_base + n4;
            float4 xv = *reinterpret_cast<const float4*>(x + off);
            float4 sv = *reinterpret_cast<const float4*>(&S[row * 136 + n4]);
            float4 rv = {sv.x + gb + xv.x, sv.y + gb + xv.y,
                         sv.z + gb + xv.z, sv.w + gb + xv.w};
            *reinterpret_cast<float4*>(out + off) = rv;
        }
        __syncthreads();
    }
}

// ---------------------------------------------------------------------------
// Launch
// ---------------------------------------------------------------------------
extern "C" void kernel_launch(void* const* d_in, const int* in_sizes, int n_in,
                              void* d_out, int out_size)
{
    const float* x     = (const float*)d_in[0];
    const float* w_q   = (const float*)d_in[1];
    const float* b_q   = (const float*)d_in[2];
    const float* w_k   = (const float*)d_in[3];
    const float* b_k   = (const float*)d_in[4];
    const float* w_v   = (const float*)d_in[5];
    const float* b_v   = (const float*)d_in[6];
    const float* w_o   = (const float*)d_in[7];
    const float* b_o   = (const float*)d_in[8];
    const float* gamma = (const float*)d_in[9];
    float* out = (float*)d_out;

    qkv_logits_kernel<<<dim3(NT, BB), 256>>>(x, w_q, b_q, w_k, b_k, w_v, b_v);
    reduce_lp_kernel<<<dim3(BB, 16), 256>>>();
    softmax_m_kernel<<<dim3(BB, 4), 256>>>(w_o, gamma);
    out_kernel<<<dim3(NN / 128, CC / 128, BB), 256>>>(x, b_o, gamma, out);
}